// round 5
// baseline (speedup 1.0000x reference)
#include <cuda_runtime.h>

// LCA sparse coding, factorized: a@G = (a@phi^T)@phi - a, G = phi^T phi - I.
// All fp32; inner loops use packed fma.rn.f32x2 (2x FFMA throughput on sm_103a).

#define MB    32      // batch (GEMM M)
#define NPIX  3072    // pixels
#define NNEU  4096    // neurons
#define NSTEP 99      // NUM_STEPS - 1
#define KT    32      // k-tile
#define TN    32      // output tile width

__device__ float g_b[MB * NNEU];
__device__ float g_u[MB * NNEU];
__device__ float g_t[MB * NPIX];

// ---------------- packed f32x2 helpers ----------------
__device__ __forceinline__ void ffma2(unsigned long long& d,
                                      unsigned long long a,
                                      unsigned long long b) {
    asm("fma.rn.f32x2 %0, %1, %2, %0;" : "+l"(d) : "l"(a), "l"(b));
}
__device__ __forceinline__ unsigned long long pack2(float x, float y) {
    unsigned long long r;
    asm("mov.b64 %0, {%1, %2};" : "=l"(r) : "f"(x), "f"(y));
    return r;
}
__device__ __forceinline__ float2 unpack2(unsigned long long v) {
    float2 r;
    asm("mov.b64 {%0, %1}, %2;" : "=f"(r.x), "=f"(r.y) : "l"(v));
    return r;
}

// ---------------- tile loaders (128 threads) ----------------
// A tile: rows m=0..31, cols k0..k0+31 of A (row-major, stride lda).
// Stored transposed + duplicated: As2[k][m] = (a, a) packed.
__device__ __forceinline__ void load_A(const float* __restrict__ A, int lda, int k0,
                                       unsigned long long (*As2)[34], int tid) {
#pragma unroll
    for (int i = 0; i < 2; i++) {
        int f  = tid + i * 128;
        int m  = f >> 3;
        int kq = (f & 7) * 4;
        float4 v = *(const float4*)(A + m * lda + k0 + kq);
        As2[kq + 0][m] = pack2(v.x, v.x);
        As2[kq + 1][m] = pack2(v.y, v.y);
        As2[kq + 2][m] = pack2(v.z, v.z);
        As2[kq + 3][m] = pack2(v.w, v.w);
    }
}

// B tile, NN case: B[k0+row][n0+col] stored directly Bs[row][col].
__device__ __forceinline__ void load_B_nn(const float* __restrict__ B, int ldb,
                                          int k0, int n0, float (*Bs)[32], int tid) {
#pragma unroll
    for (int i = 0; i < 2; i++) {
        int f   = tid + i * 128;
        int row = f >> 3;
        int col = (f & 7) * 4;
        *(float4*)&Bs[row][col] = *(const float4*)(B + (size_t)(k0 + row) * ldb + n0 + col);
    }
}

// B tile, NT case (t = a@phi^T): output dim p, reduce dim k (= neuron n).
// Load phi[p0+prow][k0+kcol] and store transposed: BsT[k][p].
__device__ __forceinline__ void load_B_nt(const float* __restrict__ B, int ldb,
                                          int p0, int k0, float (*BsT)[36], int tid) {
#pragma unroll
    for (int i = 0; i < 2; i++) {
        int f    = tid + i * 128;
        int prow = f >> 3;
        int kcol = (f & 7) * 4;
        float4 v = *(const float4*)(B + (size_t)(p0 + prow) * ldb + k0 + kcol);
        BsT[kcol + 0][prow] = v.x;
        BsT[kcol + 1][prow] = v.y;
        BsT[kcol + 2][prow] = v.z;
        BsT[kcol + 3][prow] = v.w;
    }
}

// ---------------- inner micro-kernel ----------------
// Each thread: 2 m-rows x 4 n-cols. BROW = row stride (floats) of B smem tile.
template <int BROW>
__device__ __forceinline__ void mm_inner(const unsigned long long* As2,
                                         const float* Bs,
                                         int mg, int ng,
                                         unsigned long long acc[2][2]) {
#pragma unroll
    for (int k = 0; k < KT; k++) {
        ulonglong2 ap = *(const ulonglong2*)(As2 + k * 34 + 2 * mg);
        ulonglong2 bp = *(const ulonglong2*)(Bs + k * BROW + 4 * ng);
        ffma2(acc[0][0], ap.x, bp.x);
        ffma2(acc[0][1], ap.x, bp.y);
        ffma2(acc[1][0], ap.y, bp.x);
        ffma2(acc[1][1], ap.y, bp.y);
    }
}

// ---------------- init ----------------
__global__ void k_init(float* __restrict__ a_out) {
    int i = blockIdx.x * blockDim.x + threadIdx.x;
    if (i < MB * NNEU) {
        g_u[i]  = 0.0f;
        a_out[i] = 0.0f;
    }
}

// ---------------- b = x @ phi ----------------
__global__ void __launch_bounds__(128) k_gemm_b(const float* __restrict__ x,
                                                const float* __restrict__ phi) {
    __shared__ __align__(16) unsigned long long As2[KT][34];
    __shared__ __align__(16) float Bs[KT][32];
    int tid = threadIdx.x;
    int mg = tid >> 3, ng = tid & 7;
    int n0 = blockIdx.x * TN;
    unsigned long long acc[2][2] = {{0ull, 0ull}, {0ull, 0ull}};

    for (int k0 = 0; k0 < NPIX; k0 += KT) {
        load_A(x, NPIX, k0, As2, tid);
        load_B_nn(phi, NNEU, k0, n0, Bs, tid);
        __syncthreads();
        mm_inner<32>(&As2[0][0], &Bs[0][0], mg, ng, acc);
        __syncthreads();
    }
    int n = n0 + 4 * ng;
#pragma unroll
    for (int im = 0; im < 2; im++) {
        int m = 2 * mg + im;
        float2 c0 = unpack2(acc[im][0]);
        float2 c1 = unpack2(acc[im][1]);
        *(float4*)&g_b[m * NNEU + n] = make_float4(c0.x, c0.y, c1.x, c1.y);
    }
}

// ---------------- t = a @ phi^T  (t[m,p] = sum_n a[m,n]*phi[p,n]) ----------------
__global__ void __launch_bounds__(128) k_step_t(const float* __restrict__ a,
                                                const float* __restrict__ phi) {
    __shared__ __align__(16) unsigned long long As2[KT][34];
    __shared__ __align__(16) float BsT[KT][36];
    int tid = threadIdx.x;
    int mg = tid >> 3, ng = tid & 7;
    int p0 = blockIdx.x * TN;
    unsigned long long acc[2][2] = {{0ull, 0ull}, {0ull, 0ull}};

    for (int k0 = 0; k0 < NNEU; k0 += KT) {
        load_A(a, NNEU, k0, As2, tid);
        load_B_nt(phi, NNEU, p0, k0, BsT, tid);
        __syncthreads();
        mm_inner<36>(&As2[0][0], &BsT[0][0], mg, ng, acc);
        __syncthreads();
    }
    int p = p0 + 4 * ng;
#pragma unroll
    for (int im = 0; im < 2; im++) {
        int m = 2 * mg + im;
        float2 c0 = unpack2(acc[im][0]);
        float2 c1 = unpack2(acc[im][1]);
        *(float4*)&g_t[m * NPIX + p] = make_float4(c0.x, c0.y, c1.x, c1.y);
    }
}

// ---------------- c = t @ phi, fused LCA update ----------------
// du = b - (c - a) - u ; u += eta*du ; a = soft_threshold(u, lam)
__global__ void __launch_bounds__(128) k_step_update(const float* __restrict__ phi,
                                                     const float* __restrict__ lam_ptr,
                                                     float* __restrict__ a) {
    __shared__ __align__(16) unsigned long long As2[KT][34];
    __shared__ __align__(16) float Bs[KT][32];
    int tid = threadIdx.x;
    int mg = tid >> 3, ng = tid & 7;
    int n0 = blockIdx.x * TN;
    unsigned long long acc[2][2] = {{0ull, 0ull}, {0ull, 0ull}};

    for (int k0 = 0; k0 < NPIX; k0 += KT) {
        load_A(g_t, NPIX, k0, As2, tid);
        load_B_nn(phi, NNEU, k0, n0, Bs, tid);
        __syncthreads();
        mm_inner<32>(&As2[0][0], &Bs[0][0], mg, ng, acc);
        __syncthreads();
    }

    const float lam = *lam_ptr;
    const float ETA_F = (float)(0.001 / 0.03);
    int n = n0 + 4 * ng;
#pragma unroll
    for (int im = 0; im < 2; im++) {
        int m   = 2 * mg + im;
        int idx = m * NNEU + n;
        float2 c0 = unpack2(acc[im][0]);
        float2 c1 = unpack2(acc[im][1]);
        float c[4] = {c0.x, c0.y, c1.x, c1.y};
        float4 bb = *(const float4*)&g_b[idx];
        float4 uu = *(const float4*)&g_u[idx];
        float4 aa = *(const float4*)&a[idx];
        float bv[4] = {bb.x, bb.y, bb.z, bb.w};
        float uv[4] = {uu.x, uu.y, uu.z, uu.w};
        float av[4] = {aa.x, aa.y, aa.z, aa.w};
        float un[4], an[4];
#pragma unroll
        for (int j = 0; j < 4; j++) {
            float du = bv[j] - c[j] + av[j] - uv[j];
            un[j] = uv[j] + ETA_F * du;
            an[j] = (un[j] > lam) ? (un[j] - lam)
                  : ((un[j] < -lam) ? (un[j] + lam) : 0.0f);
        }
        *(float4*)&g_u[idx] = make_float4(un[0], un[1], un[2], un[3]);
        *(float4*)&a[idx]   = make_float4(an[0], an[1], an[2], an[3]);
    }
}

// ---------------- launch ----------------
extern "C" void kernel_launch(void* const* d_in, const int* in_sizes, int n_in,
                              void* d_out, int out_size) {
    const float* x   = (const float*)d_in[0];   // [32, 3072]
    const float* phi = (const float*)d_in[1];   // [3072, 4096]
    const float* lam = (const float*)d_in[2];   // scalar
    float* a = (float*)d_out;                   // [32, 4096]

    k_init<<<(MB * NNEU + 255) / 256, 256>>>(a);
    k_gemm_b<<<NNEU / TN, 128>>>(x, phi);

    for (int s = 0; s < NSTEP; s++) {
        k_step_t<<<NPIX / TN, 128>>>(a, phi);
        k_step_update<<<NNEU / TN, 128>>>(phi, lam, a);
    }
}

// round 6
// speedup vs baseline: 1.0002x; 1.0002x over previous
#include <cuda_runtime.h>

// LCA sparse coding, factorized: a@G = (a@phi^T)@phi - a, G = phi^T phi - I.
// All fp32; inner loops use packed fma.rn.f32x2 (2x FFMA throughput on sm_103a).

#define MB    32      // batch (GEMM M)
#define NPIX  3072    // pixels
#define NNEU  4096    // neurons
#define NSTEP 99      // NUM_STEPS - 1
#define KT    32      // k-tile
#define TN    32      // output tile width

__device__ float g_b[MB * NNEU];
__device__ float g_u[MB * NNEU];
__device__ float g_t[MB * NPIX];

// ---------------- packed f32x2 helpers ----------------
__device__ __forceinline__ void ffma2(unsigned long long& d,
                                      unsigned long long a,
                                      unsigned long long b) {
    asm("fma.rn.f32x2 %0, %1, %2, %0;" : "+l"(d) : "l"(a), "l"(b));
}
__device__ __forceinline__ unsigned long long pack2(float x, float y) {
    unsigned long long r;
    asm("mov.b64 %0, {%1, %2};" : "=l"(r) : "f"(x), "f"(y));
    return r;
}
__device__ __forceinline__ float2 unpack2(unsigned long long v) {
    float2 r;
    asm("mov.b64 {%0, %1}, %2;" : "=f"(r.x), "=f"(r.y) : "l"(v));
    return r;
}

// ---------------- tile loaders (128 threads) ----------------
// A tile: rows m=0..31, cols k0..k0+31 of A (row-major, stride lda).
// Stored transposed + duplicated: As2[k][m] = (a, a) packed.
__device__ __forceinline__ void load_A(const float* __restrict__ A, int lda, int k0,
                                       unsigned long long (*As2)[34], int tid) {
#pragma unroll
    for (int i = 0; i < 2; i++) {
        int f  = tid + i * 128;
        int m  = f >> 3;
        int kq = (f & 7) * 4;
        float4 v = *(const float4*)(A + m * lda + k0 + kq);
        As2[kq + 0][m] = pack2(v.x, v.x);
        As2[kq + 1][m] = pack2(v.y, v.y);
        As2[kq + 2][m] = pack2(v.z, v.z);
        As2[kq + 3][m] = pack2(v.w, v.w);
    }
}

// B tile, NN case: B[k0+row][n0+col] stored directly Bs[row][col].
__device__ __forceinline__ void load_B_nn(const float* __restrict__ B, int ldb,
                                          int k0, int n0, float (*Bs)[32], int tid) {
#pragma unroll
    for (int i = 0; i < 2; i++) {
        int f   = tid + i * 128;
        int row = f >> 3;
        int col = (f & 7) * 4;
        *(float4*)&Bs[row][col] = *(const float4*)(B + (size_t)(k0 + row) * ldb + n0 + col);
    }
}

// B tile, NT case (t = a@phi^T): output dim p, reduce dim k (= neuron n).
// Load phi[p0+prow][k0+kcol] and store transposed: BsT[k][p].
__device__ __forceinline__ void load_B_nt(const float* __restrict__ B, int ldb,
                                          int p0, int k0, float (*BsT)[36], int tid) {
#pragma unroll
    for (int i = 0; i < 2; i++) {
        int f    = tid + i * 128;
        int prow = f >> 3;
        int kcol = (f & 7) * 4;
        float4 v = *(const float4*)(B + (size_t)(p0 + prow) * ldb + k0 + kcol);
        BsT[kcol + 0][prow] = v.x;
        BsT[kcol + 1][prow] = v.y;
        BsT[kcol + 2][prow] = v.z;
        BsT[kcol + 3][prow] = v.w;
    }
}

// ---------------- inner micro-kernel ----------------
// Each thread: 2 m-rows x 4 n-cols. BROW = row stride (floats) of B smem tile.
template <int BROW>
__device__ __forceinline__ void mm_inner(const unsigned long long* As2,
                                         const float* Bs,
                                         int mg, int ng,
                                         unsigned long long acc[2][2]) {
#pragma unroll
    for (int k = 0; k < KT; k++) {
        ulonglong2 ap = *(const ulonglong2*)(As2 + k * 34 + 2 * mg);
        ulonglong2 bp = *(const ulonglong2*)(Bs + k * BROW + 4 * ng);
        ffma2(acc[0][0], ap.x, bp.x);
        ffma2(acc[0][1], ap.x, bp.y);
        ffma2(acc[1][0], ap.y, bp.x);
        ffma2(acc[1][1], ap.y, bp.y);
    }
}

// ---------------- init ----------------
__global__ void k_init(float* __restrict__ a_out) {
    int i = blockIdx.x * blockDim.x + threadIdx.x;
    if (i < MB * NNEU) {
        g_u[i]  = 0.0f;
        a_out[i] = 0.0f;
    }
}

// ---------------- b = x @ phi ----------------
__global__ void __launch_bounds__(128) k_gemm_b(const float* __restrict__ x,
                                                const float* __restrict__ phi) {
    __shared__ __align__(16) unsigned long long As2[KT][34];
    __shared__ __align__(16) float Bs[KT][32];
    int tid = threadIdx.x;
    int mg = tid >> 3, ng = tid & 7;
    int n0 = blockIdx.x * TN;
    unsigned long long acc[2][2] = {{0ull, 0ull}, {0ull, 0ull}};

    for (int k0 = 0; k0 < NPIX; k0 += KT) {
        load_A(x, NPIX, k0, As2, tid);
        load_B_nn(phi, NNEU, k0, n0, Bs, tid);
        __syncthreads();
        mm_inner<32>(&As2[0][0], &Bs[0][0], mg, ng, acc);
        __syncthreads();
    }
    int n = n0 + 4 * ng;
#pragma unroll
    for (int im = 0; im < 2; im++) {
        int m = 2 * mg + im;
        float2 c0 = unpack2(acc[im][0]);
        float2 c1 = unpack2(acc[im][1]);
        *(float4*)&g_b[m * NNEU + n] = make_float4(c0.x, c0.y, c1.x, c1.y);
    }
}

// ---------------- t = a @ phi^T  (t[m,p] = sum_n a[m,n]*phi[p,n]) ----------------
__global__ void __launch_bounds__(128) k_step_t(const float* __restrict__ a,
                                                const float* __restrict__ phi) {
    __shared__ __align__(16) unsigned long long As2[KT][34];
    __shared__ __align__(16) float BsT[KT][36];
    int tid = threadIdx.x;
    int mg = tid >> 3, ng = tid & 7;
    int p0 = blockIdx.x * TN;
    unsigned long long acc[2][2] = {{0ull, 0ull}, {0ull, 0ull}};

    for (int k0 = 0; k0 < NNEU; k0 += KT) {
        load_A(a, NNEU, k0, As2, tid);
        load_B_nt(phi, NNEU, p0, k0, BsT, tid);
        __syncthreads();
        mm_inner<36>(&As2[0][0], &BsT[0][0], mg, ng, acc);
        __syncthreads();
    }
    int p = p0 + 4 * ng;
#pragma unroll
    for (int im = 0; im < 2; im++) {
        int m = 2 * mg + im;
        float2 c0 = unpack2(acc[im][0]);
        float2 c1 = unpack2(acc[im][1]);
        *(float4*)&g_t[m * NPIX + p] = make_float4(c0.x, c0.y, c1.x, c1.y);
    }
}

// ---------------- c = t @ phi, fused LCA update ----------------
// du = b - (c - a) - u ; u += eta*du ; a = soft_threshold(u, lam)
__global__ void __launch_bounds__(128) k_step_update(const float* __restrict__ phi,
                                                     const float* __restrict__ lam_ptr,
                                                     float* __restrict__ a) {
    __shared__ __align__(16) unsigned long long As2[KT][34];
    __shared__ __align__(16) float Bs[KT][32];
    int tid = threadIdx.x;
    int mg = tid >> 3, ng = tid & 7;
    int n0 = blockIdx.x * TN;
    unsigned long long acc[2][2] = {{0ull, 0ull}, {0ull, 0ull}};

    for (int k0 = 0; k0 < NPIX; k0 += KT) {
        load_A(g_t, NPIX, k0, As2, tid);
        load_B_nn(phi, NNEU, k0, n0, Bs, tid);
        __syncthreads();
        mm_inner<32>(&As2[0][0], &Bs[0][0], mg, ng, acc);
        __syncthreads();
    }

    const float lam = *lam_ptr;
    const float ETA_F = (float)(0.001 / 0.03);
    int n = n0 + 4 * ng;
#pragma unroll
    for (int im = 0; im < 2; im++) {
        int m   = 2 * mg + im;
        int idx = m * NNEU + n;
        float2 c0 = unpack2(acc[im][0]);
        float2 c1 = unpack2(acc[im][1]);
        float c[4] = {c0.x, c0.y, c1.x, c1.y};
        float4 bb = *(const float4*)&g_b[idx];
        float4 uu = *(const float4*)&g_u[idx];
        float4 aa = *(const float4*)&a[idx];
        float bv[4] = {bb.x, bb.y, bb.z, bb.w};
        float uv[4] = {uu.x, uu.y, uu.z, uu.w};
        float av[4] = {aa.x, aa.y, aa.z, aa.w};
        float un[4], an[4];
#pragma unroll
        for (int j = 0; j < 4; j++) {
            float du = bv[j] - c[j] + av[j] - uv[j];
            un[j] = uv[j] + ETA_F * du;
            an[j] = (un[j] > lam) ? (un[j] - lam)
                  : ((un[j] < -lam) ? (un[j] + lam) : 0.0f);
        }
        *(float4*)&g_u[idx] = make_float4(un[0], un[1], un[2], un[3]);
        *(float4*)&a[idx]   = make_float4(an[0], an[1], an[2], an[3]);
    }
}

// ---------------- launch ----------------
extern "C" void kernel_launch(void* const* d_in, const int* in_sizes, int n_in,
                              void* d_out, int out_size) {
    const float* x   = (const float*)d_in[0];   // [32, 3072]
    const float* phi = (const float*)d_in[1];   // [3072, 4096]
    const float* lam = (const float*)d_in[2];   // scalar
    float* a = (float*)d_out;                   // [32, 4096]

    k_init<<<(MB * NNEU + 255) / 256, 256>>>(a);
    k_gemm_b<<<NNEU / TN, 128>>>(x, phi);

    for (int s = 0; s < NSTEP; s++) {
        k_step_t<<<NPIX / TN, 128>>>(a, phi);
        k_step_update<<<NNEU / TN, 128>>>(phi, lam, a);
    }
}

// round 16
// speedup vs baseline: 6.2855x; 6.2845x over previous
#include <cuda_runtime.h>
#include <cuda_bf16.h>
#include <cstdint>

#define MB 32
#define NPIX 3072
#define NNEU 4096
#define NSTEP 99

// Plain row-major bf16 operand arrays (no tcgen05, no swizzled images).
__device__ __align__(16) __nv_bfloat16 g_phh[(size_t)NNEU * NPIX]; // phiT hi [n][p]
__device__ __align__(16) __nv_bfloat16 g_phl[(size_t)NNEU * NPIX]; // phiT lo
__device__ __align__(16) __nv_bfloat16 g_Gh[(size_t)NNEU * NNEU];  // G hi [m][n]
__device__ __align__(16) __nv_bfloat16 g_Gl[(size_t)NNEU * NNEU];  // G lo
__device__ __align__(16) __nv_bfloat16 g_ah[2][MB * NNEU];         // a hi [par][j][n]
__device__ __align__(16) __nv_bfloat16 g_al[2][MB * NNEU];         // a lo
__device__ float g_bt[NNEU * MB];  // b [neuron][batch]
__device__ float g_ut[NNEU * MB];  // u [neuron][batch]

// ---------------- PTX helpers (all plain sm_80+ features) ----------------
__device__ __forceinline__ uint32_t smem_u32(const void* p) {
    return (uint32_t)__cvta_generic_to_shared(p);
}
__device__ __forceinline__ void cp16(uint32_t dst, const void* src) {
    asm volatile("cp.async.cg.shared.global [%0], [%1], 16;" :: "r"(dst), "l"(src) : "memory");
}
__device__ __forceinline__ void cp_commit() {
    asm volatile("cp.async.commit_group;" ::: "memory");
}
template <int N>
__device__ __forceinline__ void cp_wait() {
    asm volatile("cp.async.wait_group %0;" :: "n"(N) : "memory");
}
__device__ __forceinline__ void ldsm4(uint32_t& r0, uint32_t& r1, uint32_t& r2, uint32_t& r3,
                                      uint32_t addr) {
    asm volatile("ldmatrix.sync.aligned.m8n8.x4.shared.b16 {%0,%1,%2,%3}, [%4];"
                 : "=r"(r0), "=r"(r1), "=r"(r2), "=r"(r3) : "r"(addr));
}
__device__ __forceinline__ void mma_bf16(float* d, uint32_t a0, uint32_t a1, uint32_t a2,
                                         uint32_t a3, uint32_t b0, uint32_t b1) {
    asm volatile(
        "mma.sync.aligned.m16n8k16.row.col.f32.bf16.bf16.f32 "
        "{%0,%1,%2,%3}, {%4,%5,%6,%7}, {%8,%9}, {%0,%1,%2,%3};"
        : "+f"(d[0]), "+f"(d[1]), "+f"(d[2]), "+f"(d[3])
        : "r"(a0), "r"(a1), "r"(a2), "r"(a3), "r"(b0), "r"(b1));
}

// ---------------- init ----------------
__global__ void k_init() {
    int i = blockIdx.x * blockDim.x + threadIdx.x;  // 131072 threads
    if (i < NNEU * MB) g_ut[i] = 0.0f;
    ((uint32_t*)g_ah)[i] = 0u;  // zero both parities: 2*32*4096 bf16 = 131072 u32
    ((uint32_t*)g_al)[i] = 0u;
}

// ---------------- prep: phi[p][n] fp32 -> phiT[n][p] bf16 hi/lo ----------------
__global__ void k_prep(const float* __restrict__ phi) {
    __shared__ float t[32][33];
    int bx = blockIdx.x, by = blockIdx.y;  // bx: neuron/32, by: pixel/32
    int tx = threadIdx.x, ty = threadIdx.y;
    for (int i = ty; i < 32; i += 8)
        t[i][tx] = phi[(size_t)(by * 32 + i) * NNEU + bx * 32 + tx];
    __syncthreads();
    for (int i = ty; i < 32; i += 8) {
        int n = bx * 32 + i, p = by * 32 + tx;
        float v = t[tx][i];
        __nv_bfloat16 h = __float2bfloat16(v);
        size_t o = (size_t)n * NPIX + p;
        g_phh[o] = h;
        g_phl[o] = __float2bfloat16(v - __bfloat162float(h));
    }
}

// ---------------- b = x @ phi (exact fp32 SIMT, one-time), writes [n][j] ----------------
__device__ __forceinline__ void ffma2(unsigned long long& d, unsigned long long a,
                                      unsigned long long b) {
    asm("fma.rn.f32x2 %0, %1, %2, %0;" : "+l"(d) : "l"(a), "l"(b));
}
__device__ __forceinline__ unsigned long long pack2(float x, float y) {
    unsigned long long r; asm("mov.b64 %0, {%1, %2};" : "=l"(r) : "f"(x), "f"(y)); return r;
}
__device__ __forceinline__ float2 unpack2(unsigned long long v) {
    float2 r; asm("mov.b64 {%0, %1}, %2;" : "=f"(r.x), "=f"(r.y) : "l"(v)); return r;
}
__global__ void __launch_bounds__(128) k_gemm_b(const float* __restrict__ x,
                                                const float* __restrict__ phi) {
    __shared__ __align__(16) unsigned long long As2[32][34];
    __shared__ __align__(16) float Bs[32][32];
    int tid = threadIdx.x, mg = tid >> 3, ng = tid & 7;
    int n0 = blockIdx.x * 32;
    unsigned long long acc[2][2] = {{0ull, 0ull}, {0ull, 0ull}};
    for (int k0 = 0; k0 < NPIX; k0 += 32) {
#pragma unroll
        for (int i = 0; i < 2; i++) {
            int f = tid + i * 128;
            int m = f >> 3, kq = (f & 7) * 4;
            float4 v = *(const float4*)(x + m * NPIX + k0 + kq);
            As2[kq + 0][m] = pack2(v.x, v.x);
            As2[kq + 1][m] = pack2(v.y, v.y);
            As2[kq + 2][m] = pack2(v.z, v.z);
            As2[kq + 3][m] = pack2(v.w, v.w);
            *(float4*)&Bs[m][kq] = *(const float4*)(phi + (size_t)(k0 + m) * NNEU + n0 + kq);
        }
        __syncthreads();
#pragma unroll
        for (int k = 0; k < 32; k++) {
            ulonglong2 ap = *(const ulonglong2*)(&As2[k][2 * mg]);
            ulonglong2 bp = *(const ulonglong2*)(&Bs[k][4 * ng]);
            ffma2(acc[0][0], ap.x, bp.x); ffma2(acc[0][1], ap.x, bp.y);
            ffma2(acc[1][0], ap.y, bp.x); ffma2(acc[1][1], ap.y, bp.y);
        }
        __syncthreads();
    }
#pragma unroll
    for (int im = 0; im < 2; im++) {
        int m = 2 * mg + im;
        float2 c0 = unpack2(acc[im][0]);
        float2 c1 = unpack2(acc[im][1]);
        float vv[4] = {c0.x, c0.y, c1.x, c1.y};
#pragma unroll
        for (int c = 0; c < 4; c++) g_bt[(size_t)(n0 + 4 * ng + c) * MB + m] = vv[c];
    }
}

// ---------------- Gpre: G[m][n] = sum_p phiT[m][p] * phiT[n][p] (3-pass split bf16) ----------------
// CTA: 128 m-rows x 64 n-cols, 8 warps (one m16 stripe each), k-chunk 64, 2-stage cp.async.
#define GP_KC 64
#define GP_SA 72                         // padded row stride (bf16 elems)
#define GP_ABY (128 * GP_SA * 2)         // 18432 B per A array
#define GP_BBY (64 * GP_SA * 2)          // 9216 B per B array
#define GP_STAGE (2 * GP_ABY + 2 * GP_BBY)
#define GP_SMEM (2 * GP_STAGE)           // 110592 B

__global__ void __launch_bounds__(256, 1) k_gpre() {
    extern __shared__ __align__(16) unsigned char sm[];
    int tid = threadIdx.x, lane = tid & 31, wid = tid >> 5;
    int m0 = blockIdx.x * 128, n0 = blockIdx.y * 64;

    auto load_stage = [&](int stg, int k0) {
        unsigned char* base = sm + stg * GP_STAGE;
#pragma unroll
        for (int i = 0; i < 12; i++) {
            int id = tid + i * 256;
            const __nv_bfloat16* src; unsigned char* dst;
            if (id < 2048) {
                int arr = id >> 10, rem = id & 1023, row = rem >> 3, ch = rem & 7;
                const __nv_bfloat16* g = arr ? g_phl : g_phh;
                src = g + (size_t)(m0 + row) * NPIX + k0 + ch * 8;
                dst = base + arr * GP_ABY + row * (GP_SA * 2) + ch * 16;
            } else {
                int id2 = id - 2048, arr = id2 >> 9, rem = id2 & 511, row = rem >> 3, ch = rem & 7;
                const __nv_bfloat16* g = arr ? g_phl : g_phh;
                src = g + (size_t)(n0 + row) * NPIX + k0 + ch * 8;
                dst = base + 2 * GP_ABY + arr * GP_BBY + row * (GP_SA * 2) + ch * 16;
            }
            cp16(smem_u32(dst), src);
        }
        cp_commit();
    };

    float acc[8][4];
#pragma unroll
    for (int t = 0; t < 8; t++)
#pragma unroll
        for (int r = 0; r < 4; r++) acc[t][r] = 0.0f;

    const int NIT = NPIX / GP_KC;  // 48
    load_stage(0, 0);
    for (int it = 0; it < NIT; it++) {
        int stg = it & 1;
        if (it + 1 < NIT) { load_stage(stg ^ 1, (it + 1) * GP_KC); cp_wait<1>(); }
        else cp_wait<0>();
        __syncthreads();
        unsigned char* base = sm + stg * GP_STAGE;
        uint32_t Ah = smem_u32(base), Al = Ah + GP_ABY;
        uint32_t Bh = Ah + 2 * GP_ABY, Bl = Bh + GP_BBY;
        uint32_t arow = (uint32_t)(wid * 16 + (lane & 15));
        uint32_t brow = (uint32_t)((lane & 7) + ((lane >> 4) << 3));
        uint32_t kb = (lane >> 3) & 1;
#pragma unroll
        for (int kk = 0; kk < 4; kk++) {
            int koff = kk * 16;
            uint32_t aoff = arow * (GP_SA * 2) + (koff + (lane >> 4) * 8) * 2;
            uint32_t ah0, ah1, ah2, ah3, al0, al1, al2, al3;
            ldsm4(ah0, ah1, ah2, ah3, Ah + aoff);
            ldsm4(al0, al1, al2, al3, Al + aoff);
            uint32_t bh0[8], bh1[8], bl0[8], bl1[8];
            uint32_t boffk = (uint32_t)(koff + kb * 8) * 2;
#pragma unroll
            for (int p = 0; p < 4; p++) {
                uint32_t bo = (p * 16 + brow) * (GP_SA * 2) + boffk;
                ldsm4(bh0[2 * p], bh1[2 * p], bh0[2 * p + 1], bh1[2 * p + 1], Bh + bo);
                ldsm4(bl0[2 * p], bl1[2 * p], bl0[2 * p + 1], bl1[2 * p + 1], Bl + bo);
            }
#pragma unroll
            for (int t = 0; t < 8; t++) {
                mma_bf16(acc[t], ah0, ah1, ah2, ah3, bh0[t], bh1[t]);
                mma_bf16(acc[t], ah0, ah1, ah2, ah3, bl0[t], bl1[t]);
                mma_bf16(acc[t], al0, al1, al2, al3, bh0[t], bh1[t]);
            }
        }
        __syncthreads();
    }
    // epilogue: split each value to hi/lo bf16, store G[m][n]
    int gid = lane >> 2, tig = lane & 3;
#pragma unroll
    for (int t = 0; t < 8; t++) {
        int gn = n0 + t * 8 + tig * 2;
#pragma unroll
        for (int rh = 0; rh < 2; rh++) {
            int gm = m0 + wid * 16 + gid + rh * 8;
            float v0 = acc[t][rh * 2 + 0], v1 = acc[t][rh * 2 + 1];
            __nv_bfloat16 h0 = __float2bfloat16(v0), h1 = __float2bfloat16(v1);
            __nv_bfloat162 hp; hp.x = h0; hp.y = h1;
            __nv_bfloat162 lp;
            lp.x = __float2bfloat16(v0 - __bfloat162float(h0));
            lp.y = __float2bfloat16(v1 - __bfloat162float(h1));
            *(__nv_bfloat162*)&g_Gh[(size_t)gm * NNEU + gn] = hp;
            *(__nv_bfloat162*)&g_Gl[(size_t)gm * NNEU + gn] = lp;
        }
    }
}

// ---------------- step: D[n][j] = sum_k G[n][k] a[j][k], fused LCA update ----------------
// Grid 128: CTA owns 32 neuron rows. 8 warps = 2 m16 stripes x 4 k-slices; smem reduce.
#define ST_KC 256
#define ST_SA 264
#define ST_RB (ST_SA * 2)       // 528 B row stride
#define ST_ABY (32 * ST_RB)     // 16896 B per array
#define ST_STAGE (4 * ST_ABY)   // 67584 B
#define ST_RED (8 * 32 * 16 * 4)
#define ST_SMEM (2 * ST_STAGE + ST_RED)  // 151552 B

__global__ void __launch_bounds__(256, 1) k_step(const float* __restrict__ lam_p,
                                                 float* __restrict__ a_out, int par) {
    extern __shared__ __align__(16) unsigned char sm[];
    int tid = threadIdx.x, lane = tid & 31, wid = tid >> 5;
    int n0 = blockIdx.x * 32;
    const __nv_bfloat16* ah = g_ah[par];
    const __nv_bfloat16* al = g_al[par];

    auto load_stage = [&](int stg, int k0) {
        unsigned char* base = sm + stg * ST_STAGE;
#pragma unroll
        for (int i = 0; i < 16; i++) {
            int id = tid + i * 256;
            int arr = id >> 10, rem = id & 1023, row = rem >> 5, ch = rem & 31;
            const __nv_bfloat16* src;
            if (arr == 0)      src = g_Gh + (size_t)(n0 + row) * NNEU + k0 + ch * 8;
            else if (arr == 1) src = g_Gl + (size_t)(n0 + row) * NNEU + k0 + ch * 8;
            else if (arr == 2) src = ah + (size_t)row * NNEU + k0 + ch * 8;
            else               src = al + (size_t)row * NNEU + k0 + ch * 8;
            cp16(smem_u32(base + arr * ST_ABY + row * ST_RB + ch * 16), src);
        }
        cp_commit();
    };

    float acc[4][4];
#pragma unroll
    for (int t = 0; t < 4; t++)
#pragma unroll
        for (int r = 0; r < 4; r++) acc[t][r] = 0.0f;

    int sp = wid & 1, ks = wid >> 1;
    const int NIT = NNEU / ST_KC;  // 16
    load_stage(0, 0);
    for (int it = 0; it < NIT; it++) {
        int stg = it & 1;
        if (it + 1 < NIT) { load_stage(stg ^ 1, (it + 1) * ST_KC); cp_wait<1>(); }
        else cp_wait<0>();
        __syncthreads();
        unsigned char* base = sm + stg * ST_STAGE;
        uint32_t Ah = smem_u32(base), Al = Ah + ST_ABY;
        uint32_t Bh = Ah + 2 * ST_ABY, Bl = Bh + ST_ABY;
        uint32_t arow = (uint32_t)(sp * 16 + (lane & 15));
        uint32_t brow = (uint32_t)((lane & 7) + ((lane >> 4) << 3));
        uint32_t kb = (lane >> 3) & 1;
#pragma unroll
        for (int kk = 0; kk < 4; kk++) {
            int koff = ks * 64 + kk * 16;
            uint32_t aoff = arow * ST_RB + (koff + (lane >> 4) * 8) * 2;
            uint32_t ah0, ah1, ah2, ah3, al0, al1, al2, al3;
            ldsm4(ah0, ah1, ah2, ah3, Ah + aoff);
            ldsm4(al0, al1, al2, al3, Al + aoff);
            uint32_t bh0[4], bh1[4], bl0[4], bl1[4];
            uint32_t boffk = (uint32_t)(koff + kb * 8) * 2;
#pragma unroll
            for (int p = 0; p < 2; p++) {
                uint32_t bo = (p * 16 + brow) * ST_RB + boffk;
                ldsm4(bh0[2 * p], bh1[2 * p], bh0[2 * p + 1], bh1[2 * p + 1], Bh + bo);
                ldsm4(bl0[2 * p], bl1[2 * p], bl0[2 * p + 1], bl1[2 * p + 1], Bl + bo);
            }
#pragma unroll
            for (int t = 0; t < 4; t++) {
                mma_bf16(acc[t], ah0, ah1, ah2, ah3, bh0[t], bh1[t]);
                mma_bf16(acc[t], ah0, ah1, ah2, ah3, bl0[t], bl1[t]);
                mma_bf16(acc[t], al0, al1, al2, al3, bh0[t], bh1[t]);
            }
        }
        __syncthreads();
    }

    // cross-warp k-slice reduction via smem
    float* RS = (float*)(sm + 2 * ST_STAGE);
#pragma unroll
    for (int i = 0; i < 16; i++) RS[(wid * 32 + lane) * 16 + i] = acc[i >> 2][i & 3];
    __syncthreads();

    // epilogue: thread t handles (nl = t>>3, j = (t&7)*4 .. +3)
    int nl = tid >> 3, jb = (tid & 7) * 4;
    int n = n0 + nl;
    const float lam = *lam_p;
    const float ETA = (float)(0.001 / 0.03);
    float4 bb = *(const float4*)&g_bt[(size_t)n * MB + jb];
    float4 uu = *(const float4*)&g_ut[(size_t)n * MB + jb];
    float bv[4] = {bb.x, bb.y, bb.z, bb.w};
    float uv[4] = {uu.x, uu.y, uu.z, uu.w};
    float un[4];
    int stripe = nl >> 4, g = nl & 15, rh = g >> 3, gid = g & 7;
#pragma unroll
    for (int e = 0; e < 4; e++) {
        int j = jb + e;
        int tt = j >> 3, jin = j & 7, tig = jin >> 1, r = rh * 2 + (jin & 1);
        int lsrc = gid * 4 + tig;
        float c = 0.0f;
#pragma unroll
        for (int s = 0; s < 4; s++) {
            int w = stripe + s * 2;
            c += RS[(w * 32 + lsrc) * 16 + tt * 4 + r];
        }
        float u = uv[e];
        float ap = (u > lam) ? u - lam : ((u < -lam) ? u + lam : 0.0f);
        float du = bv[e] - c + ap - u;
        un[e] = u + ETA * du;
        float an = (un[e] > lam) ? un[e] - lam : ((un[e] < -lam) ? un[e] + lam : 0.0f);
        a_out[(size_t)j * NNEU + n] = an;
        __nv_bfloat16 h = __float2bfloat16(an);
        g_ah[par ^ 1][(size_t)j * NNEU + n] = h;
        g_al[par ^ 1][(size_t)j * NNEU + n] = __float2bfloat16(an - __bfloat162float(h));
    }
    *(float4*)&g_ut[(size_t)n * MB + jb] = make_float4(un[0], un[1], un[2], un[3]);
}

// ---------------- launch ----------------
extern "C" void kernel_launch(void* const* d_in, const int* in_sizes, int n_in,
                              void* d_out, int out_size) {
    const float* x   = (const float*)d_in[0];
    const float* phi = (const float*)d_in[1];
    const float* lam = (const float*)d_in[2];
    float* a = (float*)d_out;

    cudaFuncSetAttribute(k_gpre, cudaFuncAttributeMaxDynamicSharedMemorySize, GP_SMEM);
    cudaFuncSetAttribute(k_step, cudaFuncAttributeMaxDynamicSharedMemorySize, ST_SMEM);

    k_init<<<512, 256>>>();
    k_prep<<<dim3(NNEU / 32, NPIX / 32), dim3(32, 8)>>>(phi);
    k_gemm_b<<<NNEU / 32, 128>>>(x, phi);
    k_gpre<<<dim3(NNEU / 128, NNEU / 64), 256, GP_SMEM>>>();
    for (int s = 0; s < NSTEP; s++)
        k_step<<<128, 256, ST_SMEM>>>(lam, a, s & 1);
}